// round 6
// baseline (speedup 1.0000x reference)
#include <cuda_runtime.h>
#include <cuda_bf16.h>

// Dynamic per-pixel depthwise 3x3 conv, stride 1, pad 1.
// input : [B=8, C=64, H=128, W=128]           float32
// weight: [B, C, 3, 3, outH=128, outW=128]    float32
// out   : [B, C, 128, 128]                    float32
//
// HBM-bound (~340 MB DRAM traffic; 302 MB is read-once weights; input stays
// L2-resident). One thread = 4 px x 2 adjacent oh rows; one warp = full
// 128-px row pair -> every global access is a perfectly coalesced 512B tx.
// Halos via warp shuffle. Plain __ldg for weights (default L2 policy measured
// faster than __ldcs: 84.3% vs 82% DRAM util across rounds).

#define B_  8
#define C_  64
#define H_  128
#define W_  128
#define HW_ (H_ * W_)
#define FULL 0xFFFFFFFFu

__global__ __launch_bounds__(256, 5)
void dydconv_kernel(const float* __restrict__ input,
                    const float* __restrict__ weight,
                    float* __restrict__ out)
{
    const int tid = blockIdx.x * blockDim.x + threadIdx.x;
    const int lane = tid & 31;
    const int ow4 = lane * 4;                // warp covers full row: 0..124
    int t = tid >> 5;
    const int oh2 = (t & 63) * 2;            // row pair: oh2, oh2+1
    const int bc = t >> 6;                   // 0..511

    // weight layout: (((bc*3 + kh)*3 + kw)*H_ + oh)*W_ + ow
    const long wbase = ((long)bc * 9) * (long)HW_ + (long)oh2 * W_ + ow4;
    const int ibase = bc * HW_ + oh2 * W_ + ow4;

    // input rows ih = oh2-1 .. oh2+2 ; [ow4-1 .. ow4+4] = 6 floats per row,
    // halos via warp shuffle (lane 0 left / lane 31 right are image borders).
    float r[4][6];
    #pragma unroll
    for (int rr = 0; rr < 4; ++rr) {
        const int ih = oh2 - 1 + rr;
        float4 v = make_float4(0.f, 0.f, 0.f, 0.f);
        if (ih >= 0 && ih < H_)
            v = __ldg(reinterpret_cast<const float4*>(input + bc * HW_ + ih * W_ + ow4));
        float left  = __shfl_up_sync(FULL, v.w, 1);
        float right = __shfl_down_sync(FULL, v.x, 1);
        if (lane == 0)  left = 0.f;
        if (lane == 31) right = 0.f;
        r[rr][0] = left;
        r[rr][1] = v.x; r[rr][2] = v.y; r[rr][3] = v.z; r[rr][4] = v.w;
        r[rr][5] = right;
    }

    float4 acc0 = make_float4(0.f, 0.f, 0.f, 0.f);  // row oh2
    float4 acc1 = make_float4(0.f, 0.f, 0.f, 0.f);  // row oh2+1

    #pragma unroll
    for (int kh = 0; kh < 3; ++kh) {
        // front-batch the 6 weight loads of this kh, then do the FMAs
        float4 w0[3], w1[3];
        #pragma unroll
        for (int kw = 0; kw < 3; ++kw) {
            const float* wp = weight + wbase + (long)(kh * 3 + kw) * HW_;
            w0[kw] = __ldg(reinterpret_cast<const float4*>(wp));       // tap row oh2
            w1[kw] = __ldg(reinterpret_cast<const float4*>(wp + W_));  // tap row oh2+1
        }
        const float* ra = r[kh];
        const float* rb = r[kh + 1];
        #pragma unroll
        for (int kw = 0; kw < 3; ++kw) {
            acc0.x = fmaf(w0[kw].x, ra[kw + 0], acc0.x);
            acc0.y = fmaf(w0[kw].y, ra[kw + 1], acc0.y);
            acc0.z = fmaf(w0[kw].z, ra[kw + 2], acc0.z);
            acc0.w = fmaf(w0[kw].w, ra[kw + 3], acc0.w);
            acc1.x = fmaf(w1[kw].x, rb[kw + 0], acc1.x);
            acc1.y = fmaf(w1[kw].y, rb[kw + 1], acc1.y);
            acc1.z = fmaf(w1[kw].z, rb[kw + 2], acc1.z);
            acc1.w = fmaf(w1[kw].w, rb[kw + 3], acc1.w);
        }
    }

    *reinterpret_cast<float4*>(out + ibase)      = acc0;
    *reinterpret_cast<float4*>(out + ibase + W_) = acc1;
}

extern "C" void kernel_launch(void* const* d_in, const int* in_sizes, int n_in,
                              void* d_out, int out_size)
{
    const float* input  = (const float*)d_in[0];
    const float* weight = (const float*)d_in[1];
    float* out = (float*)d_out;

    const int total_thr = B_ * C_ * (H_ / 2) * (W_ / 4);  // 1,048,576
    const int threads = 256;
    const int blocks = total_thr / threads;               // 4096
    dydconv_kernel<<<blocks, threads>>>(input, weight, out);
}

// round 7
// speedup vs baseline: 1.1195x; 1.1195x over previous
#include <cuda_runtime.h>
#include <cuda_bf16.h>

// Dynamic per-pixel depthwise 3x3 conv, stride 1, pad 1.
// input : [B=8, C=64, H=128, W=128]           float32
// weight: [B, C, 3, 3, outH=128, outW=128]    float32
// out   : [B, C, 128, 128]                    float32
//
// HBM-bound, traffic at floor (~340 MB: 302 MB read-once weights + L2-resident
// input + output). Measured: __ldcs on weights is REQUIRED (default policy
// evicts input from L2 -> +22 MB refetch, +3.5 us).
// One thread = 4 px x 2 adjacent oh rows; one warp = full 128-px row pair ->
// every global access is a perfectly coalesced 512B warp tx. Halos via shfl.
// Weight loads: ld.global.cs.L2::256B (evict-first + 256B prefetch) to widen
// L2 fill granularity on the pure-streaming weight path.

#define B_  8
#define C_  64
#define H_  128
#define W_  128
#define HW_ (H_ * W_)
#define FULL 0xFFFFFFFFu

__device__ __forceinline__ float4 ldcs_pf256(const float* p) {
    float4 v;
    asm volatile("ld.global.cs.L2::256B.v4.f32 {%0,%1,%2,%3}, [%4];"
                 : "=f"(v.x), "=f"(v.y), "=f"(v.z), "=f"(v.w)
                 : "l"(p));
    return v;
}

__global__ __launch_bounds__(256, 5)
void dydconv_kernel(const float* __restrict__ input,
                    const float* __restrict__ weight,
                    float* __restrict__ out)
{
    const int tid = blockIdx.x * blockDim.x + threadIdx.x;
    const int lane = tid & 31;
    const int ow4 = lane * 4;                // warp covers full row: 0..124
    int t = tid >> 5;
    const int oh2 = (t & 63) * 2;            // row pair: oh2, oh2+1
    const int bc = t >> 6;                   // 0..511

    // weight layout: (((bc*3 + kh)*3 + kw)*H_ + oh)*W_ + ow
    const long wbase = ((long)bc * 9) * (long)HW_ + (long)oh2 * W_ + ow4;
    const int ibase = bc * HW_ + oh2 * W_ + ow4;

    // input rows ih = oh2-1 .. oh2+2 ; [ow4-1 .. ow4+4] = 6 floats per row,
    // halos via warp shuffle (lane 0 left / lane 31 right are image borders).
    float r[4][6];
    #pragma unroll
    for (int rr = 0; rr < 4; ++rr) {
        const int ih = oh2 - 1 + rr;
        float4 v = make_float4(0.f, 0.f, 0.f, 0.f);
        if (ih >= 0 && ih < H_)
            v = __ldg(reinterpret_cast<const float4*>(input + bc * HW_ + ih * W_ + ow4));
        float left  = __shfl_up_sync(FULL, v.w, 1);
        float right = __shfl_down_sync(FULL, v.x, 1);
        if (lane == 0)  left = 0.f;
        if (lane == 31) right = 0.f;
        r[rr][0] = left;
        r[rr][1] = v.x; r[rr][2] = v.y; r[rr][3] = v.z; r[rr][4] = v.w;
        r[rr][5] = right;
    }

    float4 acc0 = make_float4(0.f, 0.f, 0.f, 0.f);  // row oh2
    float4 acc1 = make_float4(0.f, 0.f, 0.f, 0.f);  // row oh2+1

    #pragma unroll
    for (int kh = 0; kh < 3; ++kh) {
        #pragma unroll
        for (int kw = 0; kw < 3; ++kw) {
            const float* wp = weight + wbase + (long)(kh * 3 + kw) * HW_;
            const float4 w0 = ldcs_pf256(wp);        // tap row oh2
            const float4 w1 = ldcs_pf256(wp + W_);   // tap row oh2+1
            const float* ra = r[kh];
            const float* rb = r[kh + 1];
            acc0.x = fmaf(w0.x, ra[kw + 0], acc0.x);
            acc0.y = fmaf(w0.y, ra[kw + 1], acc0.y);
            acc0.z = fmaf(w0.z, ra[kw + 2], acc0.z);
            acc0.w = fmaf(w0.w, ra[kw + 3], acc0.w);
            acc1.x = fmaf(w1.x, rb[kw + 0], acc1.x);
            acc1.y = fmaf(w1.y, rb[kw + 1], acc1.y);
            acc1.z = fmaf(w1.z, rb[kw + 2], acc1.z);
            acc1.w = fmaf(w1.w, rb[kw + 3], acc1.w);
        }
    }

    *reinterpret_cast<float4*>(out + ibase)      = acc0;
    *reinterpret_cast<float4*>(out + ibase + W_) = acc1;
}

extern "C" void kernel_launch(void* const* d_in, const int* in_sizes, int n_in,
                              void* d_out, int out_size)
{
    const float* input  = (const float*)d_in[0];
    const float* weight = (const float*)d_in[1];
    float* out = (float*)d_out;

    const int total_thr = B_ * C_ * (H_ / 2) * (W_ / 4);  // 1,048,576
    const int threads = 256;
    const int blocks = total_thr / threads;               // 4096
    dydconv_kernel<<<blocks, threads>>>(input, weight, out);
}

// round 8
// speedup vs baseline: 1.1597x; 1.0359x over previous
#include <cuda_runtime.h>
#include <cuda_bf16.h>

// Dynamic per-pixel depthwise 3x3 conv, stride 1, pad 1.
// input : [B=8, C=64, H=128, W=128]           float32
// weight: [B, C, 3, 3, outH=128, outW=128]    float32
// out   : [B, C, 128, 128]                    float32
//
// HBM-bound, traffic at floor (~340 MB; 302 MB read-once weights dominate).
// One thread = 4 px x 2 adjacent oh rows; one warp = full 128-px row pair ->
// every global access is a perfectly coalesced 512B warp tx. Halos via shfl.
// Cache-policy discipline (all measured):
//   weights: ld.global.cs.L2::256B  (evict-first + wide fill; .cs REQUIRED —
//            default policy evicts input from L2, +22 MB refetch, +3.5 us)
//   input  : ld.global.nc.L2::256B  (cached — reused across row pairs)
//   output : st.global.cs           (write-once, evict-first)

#define B_  8
#define C_  64
#define H_  128
#define W_  128
#define HW_ (H_ * W_)
#define FULL 0xFFFFFFFFu

__device__ __forceinline__ float4 ldcs_pf256(const float* p) {
    float4 v;
    asm volatile("ld.global.cs.L2::256B.v4.f32 {%0,%1,%2,%3}, [%4];"
                 : "=f"(v.x), "=f"(v.y), "=f"(v.z), "=f"(v.w)
                 : "l"(p));
    return v;
}

__device__ __forceinline__ float4 ldnc_pf256(const float* p) {
    float4 v;
    asm volatile("ld.global.nc.L2::256B.v4.f32 {%0,%1,%2,%3}, [%4];"
                 : "=f"(v.x), "=f"(v.y), "=f"(v.z), "=f"(v.w)
                 : "l"(p));
    return v;
}

__device__ __forceinline__ void stcs4(float* p, float4 v) {
    asm volatile("st.global.cs.v4.f32 [%0], {%1,%2,%3,%4};"
                 :: "l"(p), "f"(v.x), "f"(v.y), "f"(v.z), "f"(v.w)
                 : "memory");
}

__global__ __launch_bounds__(256, 5)
void dydconv_kernel(const float* __restrict__ input,
                    const float* __restrict__ weight,
                    float* __restrict__ out)
{
    const int tid = blockIdx.x * blockDim.x + threadIdx.x;
    const int lane = tid & 31;
    const int ow4 = lane * 4;                // warp covers full row: 0..124
    int t = tid >> 5;
    const int oh2 = (t & 63) * 2;            // row pair: oh2, oh2+1
    const int bc = t >> 6;                   // 0..511

    // weight layout: (((bc*3 + kh)*3 + kw)*H_ + oh)*W_ + ow
    const long wbase = ((long)bc * 9) * (long)HW_ + (long)oh2 * W_ + ow4;
    const int ibase = bc * HW_ + oh2 * W_ + ow4;

    // input rows ih = oh2-1 .. oh2+2 ; [ow4-1 .. ow4+4] = 6 floats per row,
    // halos via warp shuffle (lane 0 left / lane 31 right are image borders).
    float r[4][6];
    #pragma unroll
    for (int rr = 0; rr < 4; ++rr) {
        const int ih = oh2 - 1 + rr;
        float4 v = make_float4(0.f, 0.f, 0.f, 0.f);
        if (ih >= 0 && ih < H_)
            v = ldnc_pf256(input + bc * HW_ + ih * W_ + ow4);
        float left  = __shfl_up_sync(FULL, v.w, 1);
        float right = __shfl_down_sync(FULL, v.x, 1);
        if (lane == 0)  left = 0.f;
        if (lane == 31) right = 0.f;
        r[rr][0] = left;
        r[rr][1] = v.x; r[rr][2] = v.y; r[rr][3] = v.z; r[rr][4] = v.w;
        r[rr][5] = right;
    }

    float4 acc0 = make_float4(0.f, 0.f, 0.f, 0.f);  // row oh2
    float4 acc1 = make_float4(0.f, 0.f, 0.f, 0.f);  // row oh2+1

    #pragma unroll
    for (int kh = 0; kh < 3; ++kh) {
        #pragma unroll
        for (int kw = 0; kw < 3; ++kw) {
            const float* wp = weight + wbase + (long)(kh * 3 + kw) * HW_;
            const float4 w0 = ldcs_pf256(wp);        // tap row oh2
            const float4 w1 = ldcs_pf256(wp + W_);   // tap row oh2+1
            const float* ra = r[kh];
            const float* rb = r[kh + 1];
            acc0.x = fmaf(w0.x, ra[kw + 0], acc0.x);
            acc0.y = fmaf(w0.y, ra[kw + 1], acc0.y);
            acc0.z = fmaf(w0.z, ra[kw + 2], acc0.z);
            acc0.w = fmaf(w0.w, ra[kw + 3], acc0.w);
            acc1.x = fmaf(w1.x, rb[kw + 0], acc1.x);
            acc1.y = fmaf(w1.y, rb[kw + 1], acc1.y);
            acc1.z = fmaf(w1.z, rb[kw + 2], acc1.z);
            acc1.w = fmaf(w1.w, rb[kw + 3], acc1.w);
        }
    }

    stcs4(out + ibase,      acc0);
    stcs4(out + ibase + W_, acc1);
}

extern "C" void kernel_launch(void* const* d_in, const int* in_sizes, int n_in,
                              void* d_out, int out_size)
{
    const float* input  = (const float*)d_in[0];
    const float* weight = (const float*)d_in[1];
    float* out = (float*)d_out;

    const int total_thr = B_ * C_ * (H_ / 2) * (W_ / 4);  // 1,048,576
    const int threads = 256;
    const int blocks = total_thr / threads;               // 4096
    dydconv_kernel<<<blocks, threads>>>(input, weight, out);
}

// round 9
// speedup vs baseline: 1.1657x; 1.0052x over previous
#include <cuda_runtime.h>
#include <cuda_bf16.h>

// Dynamic per-pixel depthwise 3x3 conv, stride 1, pad 1.
// input : [B=8, C=64, H=128, W=128]           float32
// weight: [B, C, 3, 3, outH=128, outW=128]    float32
// out   : [B, C, 128, 128]                    float32
//
// HBM-bound, traffic at floor (~339 MB = 302 MB read-once weights + 33.5 MB
// output; input is L2-resident across graph replays). Only lever left is
// achieved DRAM utilization -> raise occupancy to 6 CTAs/SM (67.5%), the one
// config that previously correlated with the session-best 84.3% DRAM.
// One thread = 4 px x 2 adjacent oh rows; one warp = full 128-px row pair ->
// every global access is a perfectly coalesced 512B warp tx. Halos via shfl.
// Cache-policy (measured): weights ld.cs.L2::256B (REQUIRED: default policy
// evicts input from L2, +22MB/+3.5us), input ld.nc.L2::256B, output st.cs.

#define B_  8
#define C_  64
#define H_  128
#define W_  128
#define HW_ (H_ * W_)
#define FULL 0xFFFFFFFFu

__device__ __forceinline__ float4 ldcs_pf256(const float* p) {
    float4 v;
    asm volatile("ld.global.cs.L2::256B.v4.f32 {%0,%1,%2,%3}, [%4];"
                 : "=f"(v.x), "=f"(v.y), "=f"(v.z), "=f"(v.w)
                 : "l"(p));
    return v;
}

__device__ __forceinline__ float4 ldnc_pf256(const float* p) {
    float4 v;
    asm volatile("ld.global.nc.L2::256B.v4.f32 {%0,%1,%2,%3}, [%4];"
                 : "=f"(v.x), "=f"(v.y), "=f"(v.z), "=f"(v.w)
                 : "l"(p));
    return v;
}

__device__ __forceinline__ void stcs4(float* p, float4 v) {
    asm volatile("st.global.cs.v4.f32 [%0], {%1,%2,%3,%4};"
                 :: "l"(p), "f"(v.x), "f"(v.y), "f"(v.z), "f"(v.w)
                 : "memory");
}

__global__ __launch_bounds__(256, 6)
void dydconv_kernel(const float* __restrict__ input,
                    const float* __restrict__ weight,
                    float* __restrict__ out)
{
    const int tid = blockIdx.x * blockDim.x + threadIdx.x;
    const int lane = tid & 31;
    const int ow4 = lane * 4;                // warp covers full row: 0..124
    int t = tid >> 5;
    const int oh2 = (t & 63) * 2;            // row pair: oh2, oh2+1
    const int bc = t >> 6;                   // 0..511

    // weight layout: (((bc*3 + kh)*3 + kw)*H_ + oh)*W_ + ow
    const long wbase = ((long)bc * 9) * (long)HW_ + (long)oh2 * W_ + ow4;
    const int ibase = bc * HW_ + oh2 * W_ + ow4;

    // input rows ih = oh2-1 .. oh2+2 ; [ow4-1 .. ow4+4] = 6 floats per row,
    // halos via warp shuffle (lane 0 left / lane 31 right are image borders).
    float r[4][6];
    #pragma unroll
    for (int rr = 0; rr < 4; ++rr) {
        const int ih = oh2 - 1 + rr;
        float4 v = make_float4(0.f, 0.f, 0.f, 0.f);
        if (ih >= 0 && ih < H_)
            v = ldnc_pf256(input + bc * HW_ + ih * W_ + ow4);
        float left  = __shfl_up_sync(FULL, v.w, 1);
        float right = __shfl_down_sync(FULL, v.x, 1);
        if (lane == 0)  left = 0.f;
        if (lane == 31) right = 0.f;
        r[rr][0] = left;
        r[rr][1] = v.x; r[rr][2] = v.y; r[rr][3] = v.z; r[rr][4] = v.w;
        r[rr][5] = right;
    }

    float4 acc0 = make_float4(0.f, 0.f, 0.f, 0.f);  // row oh2
    float4 acc1 = make_float4(0.f, 0.f, 0.f, 0.f);  // row oh2+1

    #pragma unroll
    for (int kh = 0; kh < 3; ++kh) {
        #pragma unroll
        for (int kw = 0; kw < 3; ++kw) {
            const float* wp = weight + wbase + (long)(kh * 3 + kw) * HW_;
            const float4 w0 = ldcs_pf256(wp);        // tap row oh2
            const float4 w1 = ldcs_pf256(wp + W_);   // tap row oh2+1
            const float* ra = r[kh];
            const float* rb = r[kh + 1];
            acc0.x = fmaf(w0.x, ra[kw + 0], acc0.x);
            acc0.y = fmaf(w0.y, ra[kw + 1], acc0.y);
            acc0.z = fmaf(w0.z, ra[kw + 2], acc0.z);
            acc0.w = fmaf(w0.w, ra[kw + 3], acc0.w);
            acc1.x = fmaf(w1.x, rb[kw + 0], acc1.x);
            acc1.y = fmaf(w1.y, rb[kw + 1], acc1.y);
            acc1.z = fmaf(w1.z, rb[kw + 2], acc1.z);
            acc1.w = fmaf(w1.w, rb[kw + 3], acc1.w);
        }
    }

    stcs4(out + ibase,      acc0);
    stcs4(out + ibase + W_, acc1);
}

extern "C" void kernel_launch(void* const* d_in, const int* in_sizes, int n_in,
                              void* d_out, int out_size)
{
    const float* input  = (const float*)d_in[0];
    const float* weight = (const float*)d_in[1];
    float* out = (float*)d_out;

    const int total_thr = B_ * C_ * (H_ / 2) * (W_ / 4);  // 1,048,576
    const int threads = 256;
    const int blocks = total_thr / threads;               // 4096
    dydconv_kernel<<<blocks, threads>>>(input, weight, out);
}

// round 10
// speedup vs baseline: 1.2053x; 1.0340x over previous
#include <cuda_runtime.h>
#include <cuda_bf16.h>

// Dynamic per-pixel depthwise 3x3 conv, stride 1, pad 1.
// input : [B=8, C=64, H=128, W=128]           float32
// weight: [B, C, 3, 3, outH=128, outW=128]    float32
// out   : [B, C, 128, 128]                    float32
//
// HBM-bound, traffic at floor (~335 MB = 302 MB read-once weights + 33.5 MB
// output; input L2-resident). Converged config per 9 rounds of profiles:
//  - one thread = 4 px x 2 adjacent oh rows; warp = full 128-px row pair ->
//    every global access is a perfectly coalesced 512B warp tx; shfl halos
//  - weights ld.cs.L2::256B (REQUIRED: default policy evicts input from L2,
//    +22MB refetch), input ld.nc.L2::256B, output st.cs
//  - 512-thread CTAs (2/SM): each tap-stream is 16KB contiguous per CTA and
//    stream count per SM halves -> better DRAM row-buffer locality.
//    (occ 68% measured WORSE than 56%; 40-reg squeeze reverted.)

#define B_  8
#define C_  64
#define H_  128
#define W_  128
#define HW_ (H_ * W_)
#define FULL 0xFFFFFFFFu

__device__ __forceinline__ float4 ldcs_pf256(const float* p) {
    float4 v;
    asm volatile("ld.global.cs.L2::256B.v4.f32 {%0,%1,%2,%3}, [%4];"
                 : "=f"(v.x), "=f"(v.y), "=f"(v.z), "=f"(v.w)
                 : "l"(p));
    return v;
}

__device__ __forceinline__ float4 ldnc_pf256(const float* p) {
    float4 v;
    asm volatile("ld.global.nc.L2::256B.v4.f32 {%0,%1,%2,%3}, [%4];"
                 : "=f"(v.x), "=f"(v.y), "=f"(v.z), "=f"(v.w)
                 : "l"(p));
    return v;
}

__device__ __forceinline__ void stcs4(float* p, float4 v) {
    asm volatile("st.global.cs.v4.f32 [%0], {%1,%2,%3,%4};"
                 :: "l"(p), "f"(v.x), "f"(v.y), "f"(v.z), "f"(v.w)
                 : "memory");
}

__global__ __launch_bounds__(512, 2)
void dydconv_kernel(const float* __restrict__ input,
                    const float* __restrict__ weight,
                    float* __restrict__ out)
{
    const int tid = blockIdx.x * blockDim.x + threadIdx.x;
    const int lane = tid & 31;
    const int ow4 = lane * 4;                // warp covers full row: 0..124
    int t = tid >> 5;
    const int oh2 = (t & 63) * 2;            // row pair: oh2, oh2+1
    const int bc = t >> 6;                   // 0..511

    // weight layout: (((bc*3 + kh)*3 + kw)*H_ + oh)*W_ + ow
    const long wbase = ((long)bc * 9) * (long)HW_ + (long)oh2 * W_ + ow4;
    const int ibase = bc * HW_ + oh2 * W_ + ow4;

    // input rows ih = oh2-1 .. oh2+2 ; [ow4-1 .. ow4+4] = 6 floats per row,
    // halos via warp shuffle (lane 0 left / lane 31 right are image borders).
    float r[4][6];
    #pragma unroll
    for (int rr = 0; rr < 4; ++rr) {
        const int ih = oh2 - 1 + rr;
        float4 v = make_float4(0.f, 0.f, 0.f, 0.f);
        if (ih >= 0 && ih < H_)
            v = ldnc_pf256(input + bc * HW_ + ih * W_ + ow4);
        float left  = __shfl_up_sync(FULL, v.w, 1);
        float right = __shfl_down_sync(FULL, v.x, 1);
        if (lane == 0)  left = 0.f;
        if (lane == 31) right = 0.f;
        r[rr][0] = left;
        r[rr][1] = v.x; r[rr][2] = v.y; r[rr][3] = v.z; r[rr][4] = v.w;
        r[rr][5] = right;
    }

    float4 acc0 = make_float4(0.f, 0.f, 0.f, 0.f);  // row oh2
    float4 acc1 = make_float4(0.f, 0.f, 0.f, 0.f);  // row oh2+1

    #pragma unroll
    for (int kh = 0; kh < 3; ++kh) {
        #pragma unroll
        for (int kw = 0; kw < 3; ++kw) {
            const float* wp = weight + wbase + (long)(kh * 3 + kw) * HW_;
            const float4 w0 = ldcs_pf256(wp);        // tap row oh2
            const float4 w1 = ldcs_pf256(wp + W_);   // tap row oh2+1
            const float* ra = r[kh];
            const float* rb = r[kh + 1];
            acc0.x = fmaf(w0.x, ra[kw + 0], acc0.x);
            acc0.y = fmaf(w0.y, ra[kw + 1], acc0.y);
            acc0.z = fmaf(w0.z, ra[kw + 2], acc0.z);
            acc0.w = fmaf(w0.w, ra[kw + 3], acc0.w);
            acc1.x = fmaf(w1.x, rb[kw + 0], acc1.x);
            acc1.y = fmaf(w1.y, rb[kw + 1], acc1.y);
            acc1.z = fmaf(w1.z, rb[kw + 2], acc1.z);
            acc1.w = fmaf(w1.w, rb[kw + 3], acc1.w);
        }
    }

    stcs4(out + ibase,      acc0);
    stcs4(out + ibase + W_, acc1);
}

extern "C" void kernel_launch(void* const* d_in, const int* in_sizes, int n_in,
                              void* d_out, int out_size)
{
    const float* input  = (const float*)d_in[0];
    const float* weight = (const float*)d_in[1];
    float* out = (float*)d_out;

    const int total_thr = B_ * C_ * (H_ / 2) * (W_ / 4);  // 1,048,576
    const int threads = 512;
    const int blocks = total_thr / threads;               // 2048
    dydconv_kernel<<<blocks, threads>>>(input, weight, out);
}